// round 7
// baseline (speedup 1.0000x reference)
#include <cuda_runtime.h>
#include <cstdint>

#define L_SEQ 65536
#define KC    32
#define ID    256
#define HD    512
#define OD    256
#define FH    2048          // 4*H
#define KCAT  288           // K + I
#define NB    128           // scan blocks
#define UPB   4             // hidden units per scan block (HD / NB)

// ---------------- scratch (device globals: no allocation allowed) ----------------
__device__ float g_gx[(L_SEQ + 1) * FH];      // permuted input-gate projections (+1 pad row)
__device__ float g_h [(L_SEQ + 1) * HD];      // h rows: row 0 = initial hidden; rows 1..L sentinel-poisoned
__device__ float g_B1[KCAT * FH];             // combined (W_ih @ W_ctx), K-major, gate-permuted cols
__device__ float g_bc[FH];                    // combined bias, permuted
__device__ float g_WfcT[HD * OD];             // W_fc transposed (K-major)

// morally strong, no ordering: guaranteed visible, cheap
static __device__ __forceinline__ float ldrelaxed(const float* p) {
    float v;
    asm volatile("ld.relaxed.gpu.global.f32 %0, [%1];" : "=f"(v) : "l"(p));
    return v;
}
static __device__ __forceinline__ void strelaxed(float* p, float v) {
    asm volatile("st.relaxed.gpu.global.f32 [%0], %1;" :: "l"(p), "f"(v));
}

// ---------------- init: seed h row 0, poison rows 1..L with sentinel (replay-safe) ----------------
__global__ void init_kernel(const float* __restrict__ hidden) {
    const float SENT = 1e38f;
    size_t stride = (size_t)gridDim.x * blockDim.x;
    size_t total  = (size_t)(L_SEQ + 1) * HD;
    for (size_t i = (size_t)blockIdx.x * blockDim.x + threadIdx.x; i < total; i += stride)
        g_h[i] = (i < HD) ? hidden[i] : SENT;
}

// ---------------- prep: combined matrix C[r][k] = sum_i W_ih[r][i] * W_ctx[i][k] ----------------
// gx column order permuted for the scan: n' -> (b = n'>>4, w = (n'>>2)&3, g = n'&3), row r = g*512 + b*4 + w
__global__ void prep_combine(const float* __restrict__ W_ih, const float* __restrict__ W_ctx,
                             const float* __restrict__ b_ctx, const float* __restrict__ b_ih) {
    int np = blockIdx.x;                 // 0..2047 (permuted column)
    int b = np >> 4, w = (np >> 2) & 3, g = np & 3;
    int r = g * HD + b * UPB + w;
    __shared__ float sW[ID];
    sW[threadIdx.x] = W_ih[(size_t)r * ID + threadIdx.x];
    __syncthreads();
    for (int k = threadIdx.x; k < KCAT; k += blockDim.x) {
        float acc = 0.f;
        #pragma unroll 4
        for (int i = 0; i < ID; ++i) acc = fmaf(sW[i], W_ctx[(size_t)i * KCAT + k], acc);
        g_B1[(size_t)k * FH + np] = acc;
    }
    if (threadIdx.x < 32) {
        float p = 0.f;
        for (int i = threadIdx.x; i < ID; i += 32) p = fmaf(sW[i], b_ctx[i], p);
        #pragma unroll
        for (int off = 16; off > 0; off >>= 1) p += __shfl_xor_sync(0xffffffffu, p, off);
        if (threadIdx.x == 0) g_bc[np] = p + b_ih[r];
    }
}

// ---------------- prep: transpose W_fc[O][H] -> g_WfcT[H][O] ----------------
__global__ void prep_transpose(const float* __restrict__ W_fc) {
    int k = blockIdx.x;      // 0..511
    int o = threadIdx.x;     // 0..255
    g_WfcT[(size_t)k * OD + o] = W_fc[(size_t)o * HD + k];
}

// ---------------- tiled fp32 GEMM (BM=BN=128, BK=8, 256 thr, 8x8 microtile) ----------------
#define BM 128
#define BN 128
#define BKK 8
template <bool CONCAT>
__global__ void __launch_bounds__(256) gemm_kernel(const float* __restrict__ A0,
                                                   const float* __restrict__ A1,
                                                   const float* __restrict__ bias_in,
                                                   float* __restrict__ Cout) {
    constexpr int KTOT = CONCAT ? KCAT : HD;
    constexpr int N    = CONCAT ? FH : OD;
    const float* Bmat  = CONCAT ? g_B1 : g_WfcT;
    const float* bias  = CONCAT ? g_bc : bias_in;
    float* C           = CONCAT ? g_gx : Cout;

    __shared__ float As[BKK][BM + 4];
    __shared__ float Bs[BKK][BN + 4];

    int tid = threadIdx.x;
    int tx = tid & 15, ty = tid >> 4;
    int m0 = blockIdx.y * BM, n0 = blockIdx.x * BN;
    int arow = tid >> 1, aq = tid & 1;
    int brow = tid >> 5, bcol = tid & 31;

    float acc[8][8];
    #pragma unroll
    for (int i = 0; i < 8; ++i)
        #pragma unroll
        for (int j = 0; j < 8; ++j) acc[i][j] = 0.f;

    for (int k0 = 0; k0 < KTOT; k0 += BKK) {
        int kk = k0 + aq * 4;
        float4 av;
        if (CONCAT) {
            av = (kk < KC)
               ? *(const float4*)(A0 + (size_t)(m0 + arow) * KC + kk)
               : *(const float4*)(A1 + (size_t)(m0 + arow) * ID + (kk - KC));
        } else {
            av = *(const float4*)(g_h + (size_t)(m0 + arow + 1) * HD + kk);
        }
        float4 bv = *(const float4*)(Bmat + (size_t)(k0 + brow) * N + n0 + bcol * 4);

        __syncthreads();
        As[aq * 4 + 0][arow] = av.x;
        As[aq * 4 + 1][arow] = av.y;
        As[aq * 4 + 2][arow] = av.z;
        As[aq * 4 + 3][arow] = av.w;
        *(float4*)&Bs[brow][bcol * 4] = bv;
        __syncthreads();

        #pragma unroll
        for (int p = 0; p < BKK; ++p) {
            float a[8], bb[8];
            *(float4*)&a[0]  = *(const float4*)&As[p][ty * 8];
            *(float4*)&a[4]  = *(const float4*)&As[p][ty * 8 + 4];
            *(float4*)&bb[0] = *(const float4*)&Bs[p][tx * 8];
            *(float4*)&bb[4] = *(const float4*)&Bs[p][tx * 8 + 4];
            #pragma unroll
            for (int i = 0; i < 8; ++i)
                #pragma unroll
                for (int j = 0; j < 8; ++j) acc[i][j] = fmaf(a[i], bb[j], acc[i][j]);
        }
    }

    float br_[8];
    #pragma unroll
    for (int j = 0; j < 8; ++j) br_[j] = bias[n0 + tx * 8 + j];
    #pragma unroll
    for (int i = 0; i < 8; ++i) {
        size_t row = (size_t)(m0 + ty * 8 + i);
        float4 o0 = make_float4(acc[i][0] + br_[0], acc[i][1] + br_[1], acc[i][2] + br_[2], acc[i][3] + br_[3]);
        float4 o1 = make_float4(acc[i][4] + br_[4], acc[i][5] + br_[5], acc[i][6] + br_[6], acc[i][7] + br_[7]);
        *(float4*)(C + row * N + n0 + tx * 8)     = o0;
        *(float4*)(C + row * N + n0 + tx * 8 + 4) = o1;
    }
}

// ---------------- LSTM scan: data-as-flag via RELAXED atomics (morally strong, unordered) ----------------
__global__ void __launch_bounds__(128, 1) scan_kernel(const float* __restrict__ W_hh,
                                                      const float* __restrict__ b_hh,
                                                      const float* __restrict__ cell,
                                                      float* __restrict__ hn_cn) {
    int b = blockIdx.x;
    int tid = threadIdx.x;
    int w = tid >> 5;
    int l = tid & 31;
    int unit = b * UPB + w;

    __shared__ float4 sh[2][HD / 4];   // parity-double-buffered h row

    // register-resident W_hh slice: lane l covers h indices {128k + 4l + j : k=0..3, j=0..3}
    float wreg[4][16];
    #pragma unroll
    for (int g = 0; g < 4; ++g) {
        const float* wrow = W_hh + (size_t)(g * HD + unit) * HD;
        #pragma unroll
        for (int k = 0; k < 4; ++k) {
            float4 v = *(const float4*)(wrow + k * 128 + l * 4);
            wreg[g][k * 4 + 0] = v.x; wreg[g][k * 4 + 1] = v.y;
            wreg[g][k * 4 + 2] = v.z; wreg[g][k * 4 + 3] = v.w;
        }
    }
    float bias0 = b_hh[0 * HD + unit], bias1 = b_hh[1 * HD + unit];
    float bias2 = b_hh[2 * HD + unit], bias3 = b_hh[3 * HD + unit];
    float c = cell[unit];
    float h = 0.f;

    int gx_off = b * 16 + w * 4 + l;       // valid for l < 4 (gate index = l)
    float gx_next = (l < 4) ? __ldcs(&g_gx[gx_off]) : 0.f;

    for (int t = 0; t < L_SEQ; ++t) {
        int p = t & 1;
        // poll my 4 floats of row t with independent relaxed loads (one L2 latency per round)
        {
            const float* base = g_h + (size_t)t * HD + tid * 4;
            float x, y, z, ww;
            for (;;) {
                x  = ldrelaxed(base + 0);
                y  = ldrelaxed(base + 1);
                z  = ldrelaxed(base + 2);
                ww = ldrelaxed(base + 3);
                if (fabsf(x) < 1e30f && fabsf(y) < 1e30f &&
                    fabsf(z) < 1e30f && fabsf(ww) < 1e30f) break;
            }
            sh[p][tid] = make_float4(x, y, z, ww);
        }
        __syncthreads();

        float gx_cur = gx_next;
        if (l < 4) gx_next = __ldcs(&g_gx[(size_t)(t + 1) * FH + gx_off]);  // prefetch next step

        // conflict-free LDS.128: lane l reads float4 slots l, l+32, l+64, l+96
        float hv[16];
        #pragma unroll
        for (int k = 0; k < 4; ++k) {
            float4 v = sh[p][k * 32 + l];
            hv[k * 4 + 0] = v.x; hv[k * 4 + 1] = v.y;
            hv[k * 4 + 2] = v.z; hv[k * 4 + 3] = v.w;
        }

        float acc0 = 0.f, acc1 = 0.f, acc2 = 0.f, acc3 = 0.f;
        #pragma unroll
        for (int e = 0; e < 16; ++e) {
            acc0 = fmaf(wreg[0][e], hv[e], acc0);
            acc1 = fmaf(wreg[1][e], hv[e], acc1);
            acc2 = fmaf(wreg[2][e], hv[e], acc2);
            acc3 = fmaf(wreg[3][e], hv[e], acc3);
        }
        #pragma unroll
        for (int off = 16; off > 0; off >>= 1) {
            acc0 += __shfl_xor_sync(0xffffffffu, acc0, off);
            acc1 += __shfl_xor_sync(0xffffffffu, acc1, off);
            acc2 += __shfl_xor_sync(0xffffffffu, acc2, off);
            acc3 += __shfl_xor_sync(0xffffffffu, acc3, off);
        }
        float p0 = acc0 + bias0 + __shfl_sync(0xffffffffu, gx_cur, 0);
        float p1 = acc1 + bias1 + __shfl_sync(0xffffffffu, gx_cur, 1);
        float p2 = acc2 + bias2 + __shfl_sync(0xffffffffu, gx_cur, 2);
        float p3 = acc3 + bias3 + __shfl_sync(0xffffffffu, gx_cur, 3);

        float ig = 1.f / (1.f + __expf(-p0));
        float fg = 1.f / (1.f + __expf(-p1));
        float gg = tanhf(p2);
        float og = 1.f / (1.f + __expf(-p3));
        c = fmaf(fg, c, ig * gg);
        h = og * tanhf(c);

        // publish immediately: single relaxed 4B store is the data AND the flag
        if (l == 0) strelaxed(&g_h[(size_t)(t + 1) * HD + unit], h);
    }
    if (l == 0) {
        hn_cn[unit]      = h;   // hn
        hn_cn[HD + unit] = c;   // cn
    }
}

// ---------------- in-place log-softmax over 256 features, one warp per row ----------------
__global__ void softmax_kernel(float* __restrict__ out) {
    int w = threadIdx.x >> 5, l = threadIdx.x & 31;
    size_t row = (size_t)blockIdx.x * 8 + w;
    float4* p = (float4*)(out + row * OD);
    float4 v0 = p[l];
    float4 v1 = p[32 + l];
    float m = fmaxf(fmaxf(fmaxf(v0.x, v0.y), fmaxf(v0.z, v0.w)),
                    fmaxf(fmaxf(v1.x, v1.y), fmaxf(v1.z, v1.w)));
    #pragma unroll
    for (int off = 16; off > 0; off >>= 1) m = fmaxf(m, __shfl_xor_sync(0xffffffffu, m, off));
    float s = __expf(v0.x - m) + __expf(v0.y - m) + __expf(v0.z - m) + __expf(v0.w - m)
            + __expf(v1.x - m) + __expf(v1.y - m) + __expf(v1.z - m) + __expf(v1.w - m);
    #pragma unroll
    for (int off = 16; off > 0; off >>= 1) s += __shfl_xor_sync(0xffffffffu, s, off);
    float ls = m + __logf(s);
    v0.x -= ls; v0.y -= ls; v0.z -= ls; v0.w -= ls;
    v1.x -= ls; v1.y -= ls; v1.z -= ls; v1.w -= ls;
    p[l] = v0;
    p[32 + l] = v1;
}

// ---------------- launch ----------------
extern "C" void kernel_launch(void* const* d_in, const int* in_sizes, int n_in,
                              void* d_out, int out_size) {
    const float* category = (const float*)d_in[0];
    const float* input    = (const float*)d_in[1];
    const float* hidden   = (const float*)d_in[2];
    const float* cell     = (const float*)d_in[3];
    const float* W_ctx    = (const float*)d_in[4];
    const float* b_ctx    = (const float*)d_in[5];
    const float* W_ih     = (const float*)d_in[6];
    const float* W_hh     = (const float*)d_in[7];
    const float* b_ih     = (const float*)d_in[8];
    const float* b_hh     = (const float*)d_in[9];
    const float* W_fc     = (const float*)d_in[10];
    const float* b_fc     = (const float*)d_in[11];
    float* out = (float*)d_out;

    init_kernel<<<8192, 256>>>(hidden);
    prep_combine<<<FH, 256>>>(W_ih, W_ctx, b_ctx, b_ih);
    prep_transpose<<<HD, 256>>>(W_fc);
    gemm_kernel<true><<<dim3(FH / BN, L_SEQ / BM), 256>>>(category, input, nullptr, nullptr);
    scan_kernel<<<NB, 128>>>(W_hh, b_hh, cell, out + (size_t)L_SEQ * OD);
    gemm_kernel<false><<<dim3(OD / BN, L_SEQ / BM), 256>>>(nullptr, nullptr, b_fc, out);
    softmax_kernel<<<L_SEQ / 8, 256>>>(out);
}

// round 8
// speedup vs baseline: 6.1907x; 6.1907x over previous
#include <cuda_runtime.h>
#include <cstdint>

#define L_SEQ 65536
#define KC    32
#define ID    256
#define HD    512
#define OD    256
#define FH    2048          // 4*H
#define KCAT  288           // K + I
#define NB    128           // scan blocks
#define UPB   4             // hidden units per scan block (HD / NB)
#define FSTRIDE 8           // flag stride in u32 (32B): poll word and RMW word never share a sector

// ---------------- scratch (device globals: no allocation allowed) ----------------
__device__ float g_gx[(L_SEQ + 1) * FH];          // permuted input-gate projections (+1 pad row)
__device__ float g_h [(L_SEQ + 1) * HD];          // h rows: row 0 = initial hidden, row t+1 = h_t
__device__ unsigned g_step[(L_SEQ + 1) * FSTRIDE];// per-step arrival counters, 32B apart
__device__ float g_B1[KCAT * FH];                 // combined (W_ih @ W_ctx), K-major, gate-permuted cols
__device__ float g_bc[FH];                        // combined bias, permuted
__device__ float g_WfcT[HD * OD];                 // W_fc transposed (K-major)

static __device__ __forceinline__ void strelaxed(float* p, float v) {
    asm volatile("st.relaxed.gpu.global.f32 [%0], %1;" :: "l"(p), "f"(v));
}
static __device__ __forceinline__ unsigned ldacq(const unsigned* p) {
    unsigned v;
    asm volatile("ld.acquire.gpu.global.u32 %0, [%1];" : "=r"(v) : "l"(p));
    return v;
}
static __device__ __forceinline__ void red_release_add(unsigned* p) {
    asm volatile("red.release.gpu.global.add.u32 [%0], %1;" :: "l"(p), "r"(1u));
}
static __device__ __forceinline__ float4 ldcg4(const float4* p) {
    float4 v;
    asm volatile("ld.global.cg.v4.f32 {%0,%1,%2,%3}, [%4];"
                 : "=f"(v.x), "=f"(v.y), "=f"(v.z), "=f"(v.w) : "l"(p));
    return v;
}

// ---------------- init: seed h row 0, zero all step counters (replay-safe) ----------------
__global__ void init_kernel(const float* __restrict__ hidden) {
    size_t stride = (size_t)gridDim.x * blockDim.x;
    size_t total  = (size_t)(L_SEQ + 1) * FSTRIDE;
    size_t i0 = (size_t)blockIdx.x * blockDim.x + threadIdx.x;
    for (size_t i = i0; i < total; i += stride) g_step[i] = 0u;
    if (i0 < HD) g_h[i0] = hidden[i0];
}

// ---------------- prep: combined matrix C[r][k] = sum_i W_ih[r][i] * W_ctx[i][k] ----------------
// gx column order permuted for the scan: n' -> (b = n'>>4, w = (n'>>2)&3, g = n'&3), row r = g*512 + b*4 + w
__global__ void prep_combine(const float* __restrict__ W_ih, const float* __restrict__ W_ctx,
                             const float* __restrict__ b_ctx, const float* __restrict__ b_ih) {
    int np = blockIdx.x;                 // 0..2047 (permuted column)
    int b = np >> 4, w = (np >> 2) & 3, g = np & 3;
    int r = g * HD + b * UPB + w;
    __shared__ float sW[ID];
    sW[threadIdx.x] = W_ih[(size_t)r * ID + threadIdx.x];
    __syncthreads();
    for (int k = threadIdx.x; k < KCAT; k += blockDim.x) {
        float acc = 0.f;
        #pragma unroll 4
        for (int i = 0; i < ID; ++i) acc = fmaf(sW[i], W_ctx[(size_t)i * KCAT + k], acc);
        g_B1[(size_t)k * FH + np] = acc;
    }
    if (threadIdx.x < 32) {
        float p = 0.f;
        for (int i = threadIdx.x; i < ID; i += 32) p = fmaf(sW[i], b_ctx[i], p);
        #pragma unroll
        for (int off = 16; off > 0; off >>= 1) p += __shfl_xor_sync(0xffffffffu, p, off);
        if (threadIdx.x == 0) g_bc[np] = p + b_ih[r];
    }
}

// ---------------- prep: transpose W_fc[O][H] -> g_WfcT[H][O] ----------------
__global__ void prep_transpose(const float* __restrict__ W_fc) {
    int k = blockIdx.x;      // 0..511
    int o = threadIdx.x;     // 0..255
    g_WfcT[(size_t)k * OD + o] = W_fc[(size_t)o * HD + k];
}

// ---------------- tiled fp32 GEMM (BM=BN=128, BK=8, 256 thr, 8x8 microtile) ----------------
#define BM 128
#define BN 128
#define BKK 8
template <bool CONCAT>
__global__ void __launch_bounds__(256) gemm_kernel(const float* __restrict__ A0,
                                                   const float* __restrict__ A1,
                                                   const float* __restrict__ bias_in,
                                                   float* __restrict__ Cout) {
    constexpr int KTOT = CONCAT ? KCAT : HD;
    constexpr int N    = CONCAT ? FH : OD;
    const float* Bmat  = CONCAT ? g_B1 : g_WfcT;
    const float* bias  = CONCAT ? g_bc : bias_in;
    float* C           = CONCAT ? g_gx : Cout;

    __shared__ float As[BKK][BM + 4];
    __shared__ float Bs[BKK][BN + 4];

    int tid = threadIdx.x;
    int tx = tid & 15, ty = tid >> 4;
    int m0 = blockIdx.y * BM, n0 = blockIdx.x * BN;
    int arow = tid >> 1, aq = tid & 1;
    int brow = tid >> 5, bcol = tid & 31;

    float acc[8][8];
    #pragma unroll
    for (int i = 0; i < 8; ++i)
        #pragma unroll
        for (int j = 0; j < 8; ++j) acc[i][j] = 0.f;

    for (int k0 = 0; k0 < KTOT; k0 += BKK) {
        int kk = k0 + aq * 4;
        float4 av;
        if (CONCAT) {
            av = (kk < KC)
               ? *(const float4*)(A0 + (size_t)(m0 + arow) * KC + kk)
               : *(const float4*)(A1 + (size_t)(m0 + arow) * ID + (kk - KC));
        } else {
            av = *(const float4*)(g_h + (size_t)(m0 + arow + 1) * HD + kk);
        }
        float4 bv = *(const float4*)(Bmat + (size_t)(k0 + brow) * N + n0 + bcol * 4);

        __syncthreads();
        As[aq * 4 + 0][arow] = av.x;
        As[aq * 4 + 1][arow] = av.y;
        As[aq * 4 + 2][arow] = av.z;
        As[aq * 4 + 3][arow] = av.w;
        *(float4*)&Bs[brow][bcol * 4] = bv;
        __syncthreads();

        #pragma unroll
        for (int p = 0; p < BKK; ++p) {
            float a[8], bb[8];
            *(float4*)&a[0]  = *(const float4*)&As[p][ty * 8];
            *(float4*)&a[4]  = *(const float4*)&As[p][ty * 8 + 4];
            *(float4*)&bb[0] = *(const float4*)&Bs[p][tx * 8];
            *(float4*)&bb[4] = *(const float4*)&Bs[p][tx * 8 + 4];
            #pragma unroll
            for (int i = 0; i < 8; ++i)
                #pragma unroll
                for (int j = 0; j < 8; ++j) acc[i][j] = fmaf(a[i], bb[j], acc[i][j]);
        }
    }

    float br_[8];
    #pragma unroll
    for (int j = 0; j < 8; ++j) br_[j] = bias[n0 + tx * 8 + j];
    #pragma unroll
    for (int i = 0; i < 8; ++i) {
        size_t row = (size_t)(m0 + ty * 8 + i);
        float4 o0 = make_float4(acc[i][0] + br_[0], acc[i][1] + br_[1], acc[i][2] + br_[2], acc[i][3] + br_[3]);
        float4 o1 = make_float4(acc[i][4] + br_[4], acc[i][5] + br_[5], acc[i][6] + br_[6], acc[i][7] + br_[7]);
        *(float4*)(C + row * N + n0 + tx * 8)     = o0;
        *(float4*)(C + row * N + n0 + tx * 8 + 4) = o1;
    }
}

// ---------------- LSTM scan: counter handoff, SINGLE polling thread per block ----------------
__global__ void __launch_bounds__(128, 1) scan_kernel(const float* __restrict__ W_hh,
                                                      const float* __restrict__ b_hh,
                                                      const float* __restrict__ cell,
                                                      float* __restrict__ hn_cn) {
    int b = blockIdx.x;
    int tid = threadIdx.x;
    int w = tid >> 5;
    int l = tid & 31;
    int unit = b * UPB + w;

    __shared__ float4 sh[2][HD / 4];   // parity-double-buffered h row

    // register-resident W_hh slice: lane l covers h indices {128k + 4l + j : k=0..3, j=0..3}
    float wreg[4][16];
    #pragma unroll
    for (int g = 0; g < 4; ++g) {
        const float* wrow = W_hh + (size_t)(g * HD + unit) * HD;
        #pragma unroll
        for (int k = 0; k < 4; ++k) {
            float4 v = *(const float4*)(wrow + k * 128 + l * 4);
            wreg[g][k * 4 + 0] = v.x; wreg[g][k * 4 + 1] = v.y;
            wreg[g][k * 4 + 2] = v.z; wreg[g][k * 4 + 3] = v.w;
        }
    }
    float bias0 = b_hh[0 * HD + unit], bias1 = b_hh[1 * HD + unit];
    float bias2 = b_hh[2 * HD + unit], bias3 = b_hh[3 * HD + unit];
    float c = cell[unit];
    float h = 0.f;

    int gx_off = b * 16 + w * 4 + l;       // valid for l < 4 (gate index = l)
    float gx_next = (l < 4) ? __ldcs(&g_gx[gx_off]) : 0.f;

    for (int t = 0; t < L_SEQ; ++t) {
        int p = t & 1;
        // ONE thread polls the step-t counter; everyone else waits at the barrier
        if (t > 0) {
            if (tid == 0) {
                const unsigned* fp = &g_step[(size_t)t * FSTRIDE];
                while (ldacq(fp) < (unsigned)NB) { }
            }
            __syncthreads();   // acquire (tid 0) -> bar -> whole block may read row t
        }
        // coalesced row read: thread tid loads h[4*tid .. 4*tid+3]
        sh[p][tid] = ldcg4((const float4*)(g_h + (size_t)t * HD) + tid);
        __syncthreads();

        float gx_cur = gx_next;
        if (l < 4) gx_next = __ldcs(&g_gx[(size_t)(t + 1) * FH + gx_off]);  // prefetch next step

        // conflict-free LDS.128: lane l reads float4 slots l, l+32, l+64, l+96
        float hv[16];
        #pragma unroll
        for (int k = 0; k < 4; ++k) {
            float4 v = sh[p][k * 32 + l];
            hv[k * 4 + 0] = v.x; hv[k * 4 + 1] = v.y;
            hv[k * 4 + 2] = v.z; hv[k * 4 + 3] = v.w;
        }

        float acc0 = 0.f, acc1 = 0.f, acc2 = 0.f, acc3 = 0.f;
        #pragma unroll
        for (int e = 0; e < 16; ++e) {
            acc0 = fmaf(wreg[0][e], hv[e], acc0);
            acc1 = fmaf(wreg[1][e], hv[e], acc1);
            acc2 = fmaf(wreg[2][e], hv[e], acc2);
            acc3 = fmaf(wreg[3][e], hv[e], acc3);
        }
        #pragma unroll
        for (int off = 16; off > 0; off >>= 1) {
            acc0 += __shfl_xor_sync(0xffffffffu, acc0, off);
            acc1 += __shfl_xor_sync(0xffffffffu, acc1, off);
            acc2 += __shfl_xor_sync(0xffffffffu, acc2, off);
            acc3 += __shfl_xor_sync(0xffffffffu, acc3, off);
        }
        float p0 = acc0 + bias0 + __shfl_sync(0xffffffffu, gx_cur, 0);
        float p1 = acc1 + bias1 + __shfl_sync(0xffffffffu, gx_cur, 1);
        float p2 = acc2 + bias2 + __shfl_sync(0xffffffffu, gx_cur, 2);
        float p3 = acc3 + bias3 + __shfl_sync(0xffffffffu, gx_cur, 3);

        float ig = 1.f / (1.f + __expf(-p0));
        float fg = 1.f / (1.f + __expf(-p1));
        float gg = tanhf(p2);
        float og = 1.f / (1.f + __expf(-p3));
        c = fmaf(fg, c, ig * gg);
        h = og * tanhf(c);

        // publish h, then one release-arrival for the whole block
        if (l == 0) strelaxed(&g_h[(size_t)(t + 1) * HD + unit], h);
        __syncthreads();
        if (tid == 0) red_release_add(&g_step[(size_t)(t + 1) * FSTRIDE]);
    }
    if (l == 0) {
        hn_cn[unit]      = h;   // hn
        hn_cn[HD + unit] = c;   // cn
    }
}

// ---------------- in-place log-softmax over 256 features, one warp per row ----------------
__global__ void softmax_kernel(float* __restrict__ out) {
    int w = threadIdx.x >> 5, l = threadIdx.x & 31;
    size_t row = (size_t)blockIdx.x * 8 + w;
    float4* p = (float4*)(out + row * OD);
    float4 v0 = p[l];
    float4 v1 = p[32 + l];
    float m = fmaxf(fmaxf(fmaxf(v0.x, v0.y), fmaxf(v0.z, v0.w)),
                    fmaxf(fmaxf(v1.x, v1.y), fmaxf(v1.z, v1.w)));
    #pragma unroll
    for (int off = 16; off > 0; off >>= 1) m = fmaxf(m, __shfl_xor_sync(0xffffffffu, m, off));
    float s = __expf(v0.x - m) + __expf(v0.y - m) + __expf(v0.z - m) + __expf(v0.w - m)
            + __expf(v1.x - m) + __expf(v1.y - m) + __expf(v1.z - m) + __expf(v1.w - m);
    #pragma unroll
    for (int off = 16; off > 0; off >>= 1) s += __shfl_xor_sync(0xffffffffu, s, off);
    float ls = m + __logf(s);
    v0.x -= ls; v0.y -= ls; v0.z -= ls; v0.w -= ls;
    v1.x -= ls; v1.y -= ls; v1.z -= ls; v1.w -= ls;
    p[l] = v0;
    p[32 + l] = v1;
}

// ---------------- launch ----------------
extern "C" void kernel_launch(void* const* d_in, const int* in_sizes, int n_in,
                              void* d_out, int out_size) {
    const float* category = (const float*)d_in[0];
    const float* input    = (const float*)d_in[1];
    const float* hidden   = (const float*)d_in[2];
    const float* cell     = (const float*)d_in[3];
    const float* W_ctx    = (const float*)d_in[4];
    const float* b_ctx    = (const float*)d_in[5];
    const float* W_ih     = (const float*)d_in[6];
    const float* W_hh     = (const float*)d_in[7];
    const float* b_ih     = (const float*)d_in[8];
    const float* b_hh     = (const float*)d_in[9];
    const float* W_fc     = (const float*)d_in[10];
    const float* b_fc     = (const float*)d_in[11];
    float* out = (float*)d_out;

    init_kernel<<<2048, 256>>>(hidden);
    prep_combine<<<FH, 256>>>(W_ih, W_ctx, b_ctx, b_ih);
    prep_transpose<<<HD, 256>>>(W_fc);
    gemm_kernel<true><<<dim3(FH / BN, L_SEQ / BM), 256>>>(category, input, nullptr, nullptr);
    scan_kernel<<<NB, 128>>>(W_hh, b_hh, cell, out + (size_t)L_SEQ * OD);
    gemm_kernel<false><<<dim3(OD / BN, L_SEQ / BM), 256>>>(nullptr, nullptr, b_fc, out);
    softmax_kernel<<<L_SEQ / 8, 256>>>(out);
}